// round 10
// baseline (speedup 1.0000x reference)
#include <cuda_runtime.h>
#include <cuda_bf16.h>

// inputs:  [B=32, 56, 56, C=256] fp32 ; routing: [32, 4] fp32
// out[b,h,w,j] = inputs[b,h,w, argmax(routing[b])*64 + j]  -> [32,56,56,64]
//
// R10: LDG and TMA implementations both converge at ~10-11us -> limiter is
// LTS-bank traffic (read pass + write-allocate pass + dirty-evict pass =
// ~77MB/replay). Write-through stores (__stwt) remove the evict pass and
// keep the output from polluting L2. Base config = R3 (best, 9.98us):
// 1568 blocks x 256 threads, 4x float4 per thread.

namespace {
constexpr int B       = 32;
constexpr int HW      = 56 * 56;      // 3136 pixels per batch
constexpr int ROUTES  = 4;
constexpr int V       = 16;           // float4 per output pixel (64 floats)
constexpr int CV      = 64;           // float4 per input pixel (256 floats)
constexpr int THREADS = 256;
constexpr int PER_TH  = 4;            // float4 per thread (MLP=4)
constexpr int PER_BLK = THREADS * PER_TH;                 // 1024
constexpr long long TOTAL_V4 = (long long)B * HW * V;     // 1,605,632
constexpr int BLOCKS  = (int)(TOTAL_V4 / PER_BLK);        // 1568 (exact)
constexpr int BLOCKS_PER_BATCH = BLOCKS / B;              // 49   (exact)
}

__global__ __launch_bounds__(THREADS)
void routing_gather_kernel(const float4* __restrict__ in4,
                           const float*  __restrict__ routing,
                           float4* __restrict__ out4)
{
    // Block covers PER_BLK consecutive output float4s, all within one batch.
    const int b = blockIdx.x / BLOCKS_PER_BATCH;   // const-divisor -> mulhi

    // argmax over 4 logits; uniform address across block -> L1 broadcast.
    const float* r = routing + b * ROUTES;
    float best = r[0];
    int route = 0;
#pragma unroll
    for (int k = 1; k < ROUTES; ++k) {
        float v = r[k];
        if (v > best) { best = v; route = k; }     // strict > = first-max tie
    }
    const int rbase = route * V;

    // Warp-coalesced: warp owns 128 consecutive f4, lane-stride 32.
    const int base = blockIdx.x * PER_BLK
                   + (threadIdx.x >> 5) * (32 * PER_TH)
                   + (threadIdx.x & 31);

    // 4 independent coalesced LDG.128 (front-batched), input stays L2-cached.
    float4 v[PER_TH];
#pragma unroll
    for (int k = 0; k < PER_TH; ++k) {
        int idx = base + k * 32;          // global output float4 index
        int t   = idx >> 4;               // pixel index (b*HW + pix)
        int j   = idx & (V - 1);          // float4 within pixel
        v[k] = __ldg(&in4[(long long)t * CV + rbase + j]);
    }
    // Write-through stores: one LTS traversal (no dirty allocate + evict),
    // and output bytes never evict the L2-resident input.
#pragma unroll
    for (int k = 0; k < PER_TH; ++k) {
        __stwt(&out4[base + k * 32], v[k]);
    }
}

extern "C" void kernel_launch(void* const* d_in, const int* in_sizes, int n_in,
                              void* d_out, int out_size)
{
    const float4* in4     = (const float4*)d_in[0];
    const float*  routing = (const float*)d_in[1];
    float4*       out4    = (float4*)d_out;

    routing_gather_kernel<<<BLOCKS, THREADS>>>(in4, routing, out4);
}

// round 11
// speedup vs baseline: 1.0394x; 1.0394x over previous
#include <cuda_runtime.h>
#include <cuda_bf16.h>
#include <cstdint>

// inputs:  [B=32, 56, 56, C=256] fp32 ; routing: [32, 4] fp32
// out[b,h,w,j] = inputs[b,h,w, argmax(routing[b])*64 + j]  -> [32,56,56,64]
//
// R11: R3 config (best: 1568x256, 4x float4/thread) with a software-pipelined
// ld/st schedule. Front-batched MLP_p1=4 at oe=8 trips the cross-CTA L1tex
// queue-spread mechanism (oe*MLP_p1=32 >> 16). Pipelining ld0,ld1,st0,ld2,
// st1,ld3,st2,st3 keeps 2 loads in flight (covers L2-hit latency) while
// sitting at the spread threshold (8*2=16). asm volatile pins the order.

namespace {
constexpr int B       = 32;
constexpr int HW      = 56 * 56;      // 3136 pixels per batch
constexpr int ROUTES  = 4;
constexpr int V       = 16;           // float4 per output pixel (64 floats)
constexpr int CV      = 64;           // float4 per input pixel (256 floats)
constexpr int THREADS = 256;
constexpr int PER_TH  = 4;            // float4 per thread
constexpr int PER_BLK = THREADS * PER_TH;                 // 1024
constexpr long long TOTAL_V4 = (long long)B * HW * V;     // 1,605,632
constexpr int BLOCKS  = (int)(TOTAL_V4 / PER_BLK);        // 1568 (exact)
constexpr int BLOCKS_PER_BATCH = BLOCKS / B;              // 49   (exact)
}

struct F4 { float x, y, z, w; };

__device__ __forceinline__ F4 ldg4(const float4* p)
{
    F4 r;
    asm volatile("ld.global.nc.v4.f32 {%0,%1,%2,%3}, [%4];"
                 : "=f"(r.x), "=f"(r.y), "=f"(r.z), "=f"(r.w) : "l"(p));
    return r;
}

__device__ __forceinline__ void stg4(float4* p, const F4& v)
{
    asm volatile("st.global.v4.f32 [%0], {%1,%2,%3,%4};"
                 :: "l"(p), "f"(v.x), "f"(v.y), "f"(v.z), "f"(v.w));
}

__global__ __launch_bounds__(THREADS)
void routing_gather_kernel(const float4* __restrict__ in4,
                           const float*  __restrict__ routing,
                           float4* __restrict__ out4)
{
    const int b = blockIdx.x / BLOCKS_PER_BATCH;   // const-divisor -> mulhi

    // argmax over 4 logits; uniform address across block -> L1 broadcast.
    const float* r = routing + b * ROUTES;
    float best = r[0];
    int route = 0;
#pragma unroll
    for (int k = 1; k < ROUTES; ++k) {
        float v = r[k];
        if (v > best) { best = v; route = k; }     // strict > = first-max tie
    }
    const int rbase = route * V;

    // Warp-coalesced: warp owns 128 consecutive f4, lane-stride 32.
    const int base = blockIdx.x * PER_BLK
                   + (threadIdx.x >> 5) * (32 * PER_TH)
                   + (threadIdx.x & 31);

    // Precompute all addresses.
    const float4* src[PER_TH];
    float4*       dst[PER_TH];
#pragma unroll
    for (int k = 0; k < PER_TH; ++k) {
        int idx = base + k * 32;          // global output float4 index
        int t   = idx >> 4;               // pixel index (b*HW + pix)
        int j   = idx & (V - 1);          // float4 within pixel
        src[k] = &in4[(long long)t * CV + rbase + j];
        dst[k] = &out4[idx];
    }

    // Pipelined schedule, pinned by asm volatile ordering:
    //   ld0 ld1 | st0 ld2 | st1 ld3 | st2 st3
    F4 v0 = ldg4(src[0]);
    F4 v1 = ldg4(src[1]);
    stg4(dst[0], v0);
    F4 v2 = ldg4(src[2]);
    stg4(dst[1], v1);
    F4 v3 = ldg4(src[3]);
    stg4(dst[2], v2);
    stg4(dst[3], v3);
}

extern "C" void kernel_launch(void* const* d_in, const int* in_sizes, int n_in,
                              void* d_out, int out_size)
{
    const float4* in4     = (const float4*)d_in[0];
    const float*  routing = (const float*)d_in[1];
    float4*       out4    = (float4*)d_out;

    routing_gather_kernel<<<BLOCKS, THREADS>>>(in4, routing, out4);
}

// round 12
// speedup vs baseline: 1.2610x; 1.2132x over previous
#include <cuda_runtime.h>
#include <cuda_bf16.h>
#include <cstdint>

// inputs:  [B=32, 56, 56, C=256] fp32 ; routing: [32, 4] fp32
// out[b,h,w,j] = inputs[b,h,w, argmax(routing[b])*64 + j]  -> [32,56,56,64]
//
// R12: hybrid split-path. Reads: per-thread LDG.128 (R3 shape: high MLP,
// high occupancy — what the all-TMA R9 lacked). Writes: STS -> 16KB SMEM
// tile -> one cp.async.bulk per CTA (async copy engine; off the per-thread
// store path). Tests whether rd/wr interference on the SM<->L2 path is the
// residual binder behind the ~10us plateau.

namespace {
constexpr int B       = 32;
constexpr int HW      = 56 * 56;      // 3136 pixels per batch
constexpr int ROUTES  = 4;
constexpr int V       = 16;           // float4 per output pixel (64 floats)
constexpr int CV      = 64;           // float4 per input pixel (256 floats)
constexpr int THREADS = 256;
constexpr int PER_TH  = 4;            // float4 per thread
constexpr int PER_BLK = THREADS * PER_TH;                 // 1024 f4 = 16 KB
constexpr long long TOTAL_V4 = (long long)B * HW * V;     // 1,605,632
constexpr int BLOCKS  = (int)(TOTAL_V4 / PER_BLK);        // 1568 (exact)
constexpr int BLOCKS_PER_BATCH = BLOCKS / B;              // 49   (exact)
constexpr int TILE_BYTES = PER_BLK * 16;                  // 16384
}

__global__ __launch_bounds__(THREADS)
void routing_gather_kernel(const float4* __restrict__ in4,
                           const float*  __restrict__ routing,
                           float4* __restrict__ out4)
{
    __shared__ alignas(128) float4 tile[PER_BLK];   // 16 KB, = output layout

    const int b = blockIdx.x / BLOCKS_PER_BATCH;    // const-divisor -> mulhi

    // argmax over 4 logits; uniform address across block -> L1 broadcast.
    const float* r = routing + b * ROUTES;
    float best = r[0];
    int route = 0;
#pragma unroll
    for (int k = 1; k < ROUTES; ++k) {
        float v = r[k];
        if (v > best) { best = v; route = k; }      // strict > = first-max tie
    }
    const int rbase = route * V;

    // Warp-coalesced: warp owns 128 consecutive f4, lane-stride 32.
    const int local = (threadIdx.x >> 5) * (32 * PER_TH) + (threadIdx.x & 31);
    const int base  = blockIdx.x * PER_BLK + local;

    // 4 independent coalesced LDG.128 (front-batched), then STS into the
    // tile at the exact output layout (conflict-free: lane->consecutive 16B).
    float4 v[PER_TH];
#pragma unroll
    for (int k = 0; k < PER_TH; ++k) {
        int idx = base + k * 32;          // global output float4 index
        int t   = idx >> 4;               // pixel index (b*HW + pix)
        int j   = idx & (V - 1);          // float4 within pixel
        v[k] = __ldg(&in4[(long long)t * CV + rbase + j]);
    }
#pragma unroll
    for (int k = 0; k < PER_TH; ++k) {
        tile[local + k * 32] = v[k];
    }
    __syncthreads();

    // One bulk async store per CTA: 16KB SMEM -> GMEM via the copy engine.
    if (threadIdx.x == 0) {
        uint32_t st = (uint32_t)__cvta_generic_to_shared(tile);
        float4* dst = out4 + (long long)blockIdx.x * PER_BLK;
        asm volatile("fence.proxy.async.shared::cta;" ::: "memory");
        asm volatile("cp.async.bulk.global.shared::cta.bulk_group [%0], [%1], %2;"
                     :: "l"(dst), "r"(st), "r"(TILE_BYTES) : "memory");
        asm volatile("cp.async.bulk.commit_group;" ::: "memory");
        asm volatile("cp.async.bulk.wait_group 0;" ::: "memory");
    }
    // Implicit: CTA may not exit before thread 0 passes wait_group (SMEM must
    // stay live for the bulk read); other threads exiting is fine — the CTA's
    // SMEM is retained until ALL threads exit, and they sync'd above.
}

extern "C" void kernel_launch(void* const* d_in, const int* in_sizes, int n_in,
                              void* d_out, int out_size)
{
    const float4* in4     = (const float4*)d_in[0];
    const float*  routing = (const float*)d_in[1];
    float4*       out4    = (float4*)d_out;

    routing_gather_kernel<<<BLOCKS, THREADS>>>(in4, routing, out4);
}